// round 4
// baseline (speedup 1.0000x reference)
#include <cuda_runtime.h>

// lut_kernel_49538152792187 — 6-bit soft-LUT layer.
// x: [16, 2, 1024, 384] f32   (d_in[0])
// w: [1024, 64, 64]     f32   (d_in[1])
// out: [16, 2, 1024, 64] f32
//
// One thread per (out, lut); wq table folded into 64 persistent regs
// (pair-packed for f32x2 level-0); 32-replica loop with DEPTH-2 load
// pipeline; level 0 done as 16x FFMA2 (fma.rn.f32x2), levels 1..5 scalar.
// w read exactly once, zero smem. Warp = 32 consecutive luts of one out
// => coalesced 768B x spans and 128B output stores.

#define OUTN 1024
#define LUTN 64
#define BR 32

__device__ __forceinline__ float sig2(float v) {
    // (tanh(v)+1)/2 == 1/(1+exp(-2v)); randn v -> bounded, no overflow.
    float e = __expf(-2.0f * v);
    return __fdividef(1.0f, 1.0f + e);
}

__device__ __forceinline__ unsigned long long pk2(float lo, float hi) {
    unsigned long long r;
    asm("mov.b64 %0, {%1, %2};" : "=l"(r) : "f"(lo), "f"(hi));
    return r;
}
__device__ __forceinline__ void upk2(float& lo, float& hi, unsigned long long v) {
    asm("mov.b64 {%0, %1}, %2;" : "=f"(lo), "=f"(hi) : "l"(v));
}
__device__ __forceinline__ unsigned long long fma2(unsigned long long a,
                                                   unsigned long long b,
                                                   unsigned long long c) {
    unsigned long long r;
    asm("fma.rn.f32x2 %0, %1, %2, %3;" : "=l"(r) : "l"(a), "l"(b), "l"(c));
    return r;
}

__global__ void __launch_bounds__(64, 7)
lut_kernel(const float* __restrict__ x, const float* __restrict__ w,
           float* __restrict__ out) {
    const int t   = blockIdx.x * 64 + threadIdx.x;   // 0 .. 65535
    const int lut = t & (LUTN - 1);
    const int o   = t >> 6;                          // out index

    // ---- load table, wq = sigmoid(2w), fold level 0, pair-pack ----
    // y0p[m] = {y0[2m], y0[2m+1]},  dp[m] = {d[2m], d[2m+1]}
    const float4* wp = reinterpret_cast<const float4*>(w + (size_t)t * 64);
    unsigned long long y0p[16], dp[16];
#pragma unroll
    for (int i = 0; i < 16; i++) {
        float4 v = wp[i];
        float q0 = sig2(v.x), q1 = sig2(v.y), q2 = sig2(v.z), q3 = sig2(v.w);
        y0p[i] = pk2(q0, q2);
        dp[i]  = pk2(q1 - q0, q3 - q2);
    }

    const float* xp = x + (size_t)o * 384 + lut * 6;   // 8B-aligned (lut*24B)
    float*       op = out + (size_t)o * 64 + lut;
    const size_t xs = (size_t)OUTN * 384;              // stride between replicas
    const size_t os = (size_t)OUTN * 64;

    // ---- depth-2 load pipeline: slots for iters i, i+1 in flight ----
    float2 A0[2], A1[2], A2[2];
    A0[0] = *reinterpret_cast<const float2*>(xp);
    A1[0] = *reinterpret_cast<const float2*>(xp + 2);
    A2[0] = *reinterpret_cast<const float2*>(xp + 4);
    xp += xs;
    A0[1] = *reinterpret_cast<const float2*>(xp);
    A1[1] = *reinterpret_cast<const float2*>(xp + 2);
    A2[1] = *reinterpret_cast<const float2*>(xp + 4);
    xp += xs;

#pragma unroll 4
    for (int br = 0; br < BR; br++) {
        const int s = br & 1;
        float2 b0 = A0[s], b1 = A1[s], b2 = A2[s];
        if (br + 2 < BR) {                 // issue loads for iter br+2
            A0[s] = *reinterpret_cast<const float2*>(xp);
            A1[s] = *reinterpret_cast<const float2*>(xp + 2);
            A2[s] = *reinterpret_cast<const float2*>(xp + 4);
            xp += xs;
        }

        // level 0: 16x FFMA2 (bit broadcast into both lanes)
        unsigned long long bb = pk2(b0.x, b0.x);
        float y[32];
#pragma unroll
        for (int m = 0; m < 16; m++) {
            unsigned long long yp = fma2(bb, dp[m], y0p[m]);
            upk2(y[2 * m], y[2 * m + 1], yp);
        }
        // level 1
#pragma unroll
        for (int j = 0; j < 16; j++) y[j] = fmaf(b0.y, y[2 * j + 1] - y[2 * j], y[2 * j]);
        // level 2
#pragma unroll
        for (int j = 0; j < 8; j++)  y[j] = fmaf(b1.x, y[2 * j + 1] - y[2 * j], y[2 * j]);
        // level 3
#pragma unroll
        for (int j = 0; j < 4; j++)  y[j] = fmaf(b1.y, y[2 * j + 1] - y[2 * j], y[2 * j]);
        // level 4
#pragma unroll
        for (int j = 0; j < 2; j++)  y[j] = fmaf(b2.x, y[2 * j + 1] - y[2 * j], y[2 * j]);
        // level 5
        float r = fmaf(b2.y, y[1] - y[0], y[0]);

        *op = r;
        op += os;
    }
}

extern "C" void kernel_launch(void* const* d_in, const int* in_sizes, int n_in,
                              void* d_out, int out_size) {
    const float* x = (const float*)d_in[0];
    const float* w = (const float*)d_in[1];
    float* out = (float*)d_out;
    lut_kernel<<<(OUTN * LUTN) / 64, 64>>>(x, w, out);
}

// round 9
// speedup vs baseline: 1.1065x; 1.1065x over previous
#include <cuda_runtime.h>

// lut_kernel_49538152792187 — 6-bit soft-LUT layer.
// x: [16, 2, 1024, 384] f32   out: [16, 2, 1024, 64] f32
// w: [1024, 64, 64]     f32
//
// TWO threads per (out, lut): each owns one 32-entry half-subtree
// (tree levels 0-4); halves combined at level 5 via shfl. Levels 0+1 are
// folded into a bilinear table (c0..c3 per 4-entry group, 32 regs):
//   y = c0 + b0*c1 + b1*c2 + (b0*b1)*c3        (3 FFMA / group)
// 131072 threads = 4096 warps (~26/SM) for latency hiding; w read exactly
// once, x deduped in-warp via broadcast (paired lanes, same address).

#define BR 32

__device__ __forceinline__ float sig2(float v) {
    // (tanh(v)+1)/2 == 1/(1+exp(-2v)); randn v -> bounded, no overflow.
    float e = __expf(-2.0f * v);
    return __fdividef(1.0f, 1.0f + e);
}

__global__ void __launch_bounds__(64, 13)
lut_kernel(const float* __restrict__ x, const float* __restrict__ w,
           float* __restrict__ out) {
    const int g    = blockIdx.x * 64 + threadIdx.x;   // 0..131071
    const int half = g & 1;                           // subtree half
    const int ol   = g >> 1;                          // o*64 + lut, 0..65535
    const int lut  = ol & 63;
    const int o    = ol >> 6;

    // ---- load 32-entry half table, wq = sigmoid(2w), fold levels 0+1 ----
    const float4* wp = reinterpret_cast<const float4*>(
        w + (size_t)ol * 64 + half * 32);
    float c0[8], c1[8], c2[8], c3[8];
#pragma unroll
    for (int m = 0; m < 8; m++) {
        float4 v = wp[m];
        float q0 = sig2(v.x), q1 = sig2(v.y), q2 = sig2(v.z), q3 = sig2(v.w);
        c0[m] = q0;
        c1[m] = q1 - q0;
        c2[m] = q2 - q0;
        c3[m] = ((q3 - q2) - q1) + q0;
    }

    const float* xp = x + (size_t)o * 384 + lut * 6;  // 8B-aligned
    float*       op = out + (size_t)ol;
    const size_t xs = (size_t)1024 * 384;
    const size_t os = (size_t)1024 * 64;

    // depth-1 prefetch
    float2 a0 = *reinterpret_cast<const float2*>(xp);
    float2 a1 = *reinterpret_cast<const float2*>(xp + 2);
    float2 a2 = *reinterpret_cast<const float2*>(xp + 4);
    xp += xs;

#pragma unroll 4
    for (int br = 0; br < BR; br++) {
        const float B0 = a0.x, B1 = a0.y, B2 = a1.x,
                    B3 = a1.y, B4 = a2.x, B5 = a2.y;
        if (br + 1 < BR) {                 // prefetch next replica's bits
            a0 = *reinterpret_cast<const float2*>(xp);
            a1 = *reinterpret_cast<const float2*>(xp + 2);
            a2 = *reinterpret_cast<const float2*>(xp + 4);
            xp += xs;
        }

        // levels 0+1 via bilinear table: 8 groups
        const float t01 = B0 * B1;
        float ym[8];
#pragma unroll
        for (int m = 0; m < 8; m++)
            ym[m] = fmaf(t01, c3[m], fmaf(B1, c2[m], fmaf(B0, c1[m], c0[m])));

        // level 2
        float z0 = fmaf(B2, ym[1] - ym[0], ym[0]);
        float z1 = fmaf(B2, ym[3] - ym[2], ym[2]);
        float z2 = fmaf(B2, ym[5] - ym[4], ym[4]);
        float z3 = fmaf(B2, ym[7] - ym[6], ym[6]);
        // level 3
        float u0 = fmaf(B3, z1 - z0, z0);
        float u1 = fmaf(B3, z3 - z2, z2);
        // level 4: this half-subtree's value
        float v = fmaf(B4, u1 - u0, u0);

        // level 5: combine halves (even lane = low half, odd = high half)
        float vhi = __shfl_down_sync(0xffffffffu, v, 1);
        if (half == 0) *op = fmaf(B5, vhi - v, v);
        op += os;
    }
}

extern "C" void kernel_launch(void* const* d_in, const int* in_sizes, int n_in,
                              void* d_out, int out_size) {
    const float* x = (const float*)d_in[0];
    const float* w = (const float*)d_in[1];
    float* out = (float*)d_out;
    lut_kernel<<<2048, 64>>>(x, w, out);
}